// round 16
// baseline (speedup 1.0000x reference)
#include <cuda_runtime.h>
#include <cuda_bf16.h>
#include <cstdint>

#define TPB 128

// B-matrix for the GEMM, PERMUTED row order: row c encodes (w,m):
//   c = w*8 + m        for m in 0..7
//   c = 32 + w         for m == 8
//   rows 36..39 stay zero.
// k-cols: 0..8 = Ghi[n], 9..17 = Glo[n], 18..26 = Ghi[n], 27..31 zero.
// Zero-initialized at module load; setup writes only nonzero entries.
__device__ __align__(16) unsigned short gB16[40 * 32];
// Publish flag: 0 only before the very first launch; replays never wait.
__device__ int gFlag = 0;

// ---------------- helpers ----------------
__device__ __forceinline__ uint32_t smem_u32(const void* p) {
    uint32_t a;
    asm("{ .reg .u64 t; cvta.to.shared.u64 t, %1; cvt.u32.u64 %0, t; }"
        : "=r"(a) : "l"(p));
    return a;
}
__device__ __forceinline__ void sts128(uint32_t addr, uint32_t a, uint32_t b,
                                       uint32_t c, uint32_t d) {
    asm volatile("st.shared.v4.b32 [%0], {%1,%2,%3,%4};"
                 :: "r"(addr), "r"(a), "r"(b), "r"(c), "r"(d) : "memory");
}
__device__ __forceinline__ void ldm_x4(uint32_t* r, uint32_t addr) {
    asm volatile("ldmatrix.sync.aligned.m8n8.x4.shared.b16 {%0,%1,%2,%3}, [%4];"
                 : "=r"(r[0]), "=r"(r[1]), "=r"(r[2]), "=r"(r[3]) : "r"(addr));
}
__device__ __forceinline__ void ldm_x2(uint32_t& b0, uint32_t& b1, uint32_t addr) {
    asm volatile("ldmatrix.sync.aligned.m8n8.x2.shared.b16 {%0,%1}, [%2];"
                 : "=r"(b0), "=r"(b1) : "r"(addr));
}
__device__ __forceinline__ void mma16816(float* d, const uint32_t* a,
                                         uint32_t b0, uint32_t b1) {
    asm volatile(
        "mma.sync.aligned.m16n8k16.row.col.f32.bf16.bf16.f32 "
        "{%0,%1,%2,%3}, {%4,%5,%6,%7}, {%8,%9}, {%0,%1,%2,%3};"
        : "+f"(d[0]), "+f"(d[1]), "+f"(d[2]), "+f"(d[3])
        : "r"(a[0]), "r"(a[1]), "r"(a[2]), "r"(a[3]), "r"(b0), "r"(b1));
}

// ---------------- shared layout (dynamic) ----------------
// A: [0, 10240)      128 rows x 80B (64B data + 16B pad; conflict-free)
//                    (block-0 setup scratch overlays this, dead before A-STS)
// B: [10240, 13440)  40 rows x 80B
#define SM_A 0
#define SM_B 10240
#define SM_TOTAL 13440

__global__ void __launch_bounds__(TPB, 6) qmma_kernel(
    const float4* __restrict__ xin, float4* __restrict__ xout,
    const float* __restrict__ qw, int nlayers, int nSamples) {
    extern __shared__ char sm[];
    const uint32_t smb = smem_u32(sm);
    const int tid = threadIdx.x;
    const int wid = tid >> 5;
    const int lane = tid & 31;

    // ================= block 0: build circuit constants =================
    if (blockIdx.x == 0) {
        float (*Mr)[16] = (float(*)[16])(sm);
        float (*Mi)[16] = (float(*)[16])(sm + 1024);
        float* bufA = (float*)(sm + 2048) + wid * 256;
        float* bufB = (float*)(sm + 6144) + wid * 192;

        if (tid < 16) {
            float mr[16], mi[16];
#pragma unroll
            for (int r = 0; r < 16; r++) { mr[r] = (r == tid) ? 1.0f : 0.0f; mi[r] = 0.0f; }
            for (int l = 0; l < nlayers; l++) {
#pragma unroll
                for (int w = 0; w < 4; w++) {
                    float phi = qw[(l * 4 + w) * 3 + 0];
                    float th  = qw[(l * 4 + w) * 3 + 1];
                    float om  = qw[(l * 4 + w) * 3 + 2];
                    float c, s, ca, sa, cb, sb;
                    __sincosf(0.5f * th, &s, &c);
                    __sincosf(0.5f * (phi + om), &sa, &ca);
                    __sincosf(0.5f * (phi - om), &sb, &cb);
                    float g00r =  ca * c, g00i = -sa * c;
                    float g01r = -cb * s, g01i = -sb * s;
                    float g10r =  cb * s, g10i = -sb * s;
                    float g11r =  ca * c, g11i =  sa * c;
                    const int mu = 8 >> w;
#pragma unroll
                    for (int r = 0; r < 16; r++) {
                        if (r & mu) continue;
                        const int r1 = r | mu;
                        float ar = mr[r],  ai = mi[r];
                        float br = mr[r1], bi = mi[r1];
                        mr[r]  = g00r * ar - g00i * ai + g01r * br - g01i * bi;
                        mi[r]  = g00r * ai + g00i * ar + g01r * bi + g01i * br;
                        mr[r1] = g10r * ar - g10i * ai + g11r * br - g11i * bi;
                        mi[r1] = g10r * ai + g10i * ar + g11r * bi + g11i * br;
                    }
                }
#pragma unroll
                for (int w = 0; w < 4; w++) {
                    const int cm = 8 >> w;
                    const int tm = 8 >> ((w + 1) & 3);
#pragma unroll
                    for (int r = 0; r < 16; r++) {
                        if ((r & cm) && !(r & tm)) {
                            const int r2 = r | tm;
                            float t;
                            t = mr[r]; mr[r] = mr[r2]; mr[r2] = t;
                            t = mi[r]; mi[r] = mi[r2]; mi[r2] = t;
                        }
                    }
                }
            }
#pragma unroll
            for (int r = 0; r < 16; r++) { Mr[r][tid] = mr[r]; Mi[r][tid] = mi[r]; }
        }
        __syncthreads();

        {   // warp w builds G_w (9x9 in (1,C,S) basis) -> permuted split rows
            const int w = wid;
            const int mw = 8 >> w;
            for (int e = lane; e < 256; e += 32) {
                int i = e / 16, j = e % 16;
                float sum = 0.0f;
                for (int k = 0; k < 16; k++) {
                    float sgn = (k & mw) ? -1.0f : 1.0f;
                    sum += sgn * (Mr[k][i] * Mr[k][j] + Mi[k][i] * Mi[k][j]);
                }
                int b0 = 0;
                for (int q = 0; q < 4; q++) {
                    int iw = (i >> (3 - q)) & 1;
                    int jw = (j >> (3 - q)) & 1;
                    b0 = b0 * 4 + (iw * 2 + jw);
                }
                bufA[b0] = sum;
            }
            __syncwarp();
            float* bin = bufA;
            float* bout = bufB;
            int pre = 1, post = 64;
            for (int q = 0; q < 4; q++) {
                int nout = pre * 3 * post;
                for (int e = lane; e < nout; e += 32) {
                    int po = e % post;
                    int al = (e / post) % 3;
                    int pr2 = e / (post * 3);
                    const float* ip = bin + pr2 * 4 * post;
                    float v;
                    if (al == 0)      v = 0.5f * (ip[0 * post + po] + ip[3 * post + po]);
                    else if (al == 1) v = 0.5f * (ip[0 * post + po] - ip[3 * post + po]);
                    else              v = 0.5f * (ip[1 * post + po] + ip[2 * post + po]);
                    bout[pr2 * 3 * post + al * post + po] = v;
                }
                __syncwarp();
                float* t = bin; bin = bout; bout = t;
                pre *= 3; post /= 4;
            }
            // bin[m*9+n] = G_w[m][n]; write permuted bf16 split rows
            for (int e = lane; e < 81; e += 32) {
                int m = e / 9, n = e % 9;
                float v = bin[e];
                __nv_bfloat16 h = __float2bfloat16(v);
                float hf = __bfloat162float(h);
                __nv_bfloat16 l2 = __float2bfloat16(v - hf);
                int row = (m < 8) ? (w * 8 + m) : (32 + w);
                gB16[row * 32 + n]      = __bfloat16_as_ushort(h);
                gB16[row * 32 + 9 + n]  = __bfloat16_as_ushort(l2);
                gB16[row * 32 + 18 + n] = __bfloat16_as_ushort(h);
            }
        }
        __syncthreads();
        if (tid == 0) {
            __threadfence();
            int one = 1;
            asm volatile("st.release.gpu.global.s32 [%0], %1;"
                         :: "l"(&gFlag), "r"(one) : "memory");
        }
        __syncthreads();   // setup scratch dead before A writes
    }

    // ================= per-sample features -> A row =================
    int idx = blockIdx.x * TPB + tid;
    int lidx = (idx < nSamples) ? idx : (nSamples - 1);
    float4 x = xin[lidx];
    float c0, s0, c1, s1, c2, s2, c3, s3;
    __sincosf(x.x, &s0, &c0);
    __sincosf(x.y, &s1, &c1);
    __sincosf(x.z, &s2, &c2);
    __sincosf(x.w, &s3, &c3);

    {
        float P[9];
        P[0] = 1.0f; P[1] = c3;      P[2] = s3;
        P[3] = c2;   P[4] = c2 * c3; P[5] = c2 * s3;
        P[6] = s2;   P[7] = s2 * c3; P[8] = s2 * s3;

        unsigned short F[32];
#pragma unroll
        for (int k = 0; k < 32; k++) F[k] = 0;
#pragma unroll
        for (int n = 0; n < 9; n++) {
            __nv_bfloat16 h = __float2bfloat16(P[n]);
            float hf = __bfloat162float(h);
            __nv_bfloat16 l2 = __float2bfloat16(P[n] - hf);
            unsigned short hb = __bfloat16_as_ushort(h);
            F[n] = hb;
            F[9 + n] = hb;
            F[18 + n] = __bfloat16_as_ushort(l2);
        }
        uint32_t w32[16];
#pragma unroll
        for (int j = 0; j < 16; j++)
            w32[j] = (uint32_t)F[2 * j] | ((uint32_t)F[2 * j + 1] << 16);

        uint32_t base = smb + SM_A + (uint32_t)tid * 80;
        sts128(base,      w32[0],  w32[1],  w32[2],  w32[3]);
        sts128(base + 16, w32[4],  w32[5],  w32[6],  w32[7]);
        sts128(base + 32, w32[8],  w32[9],  w32[10], w32[11]);
        sts128(base + 48, w32[12], w32[13], w32[14], w32[15]);
    }

    // ================= shuffle stage-2 trig from row-owner lanes ==========
    const int g = lane >> 2;
    const int t = lane & 3;
    float uc0[4], us0[4], uc1[4], us1[4];
#pragma unroll
    for (int s = 0; s < 4; s++) {
        int src = (s >> 1) * 16 + (s & 1) * 8 + g;
        uc0[s] = __shfl_sync(0xffffffffu, c0, src);
        us0[s] = __shfl_sync(0xffffffffu, s0, src);
        uc1[s] = __shfl_sync(0xffffffffu, c1, src);
        us1[s] = __shfl_sync(0xffffffffu, s1, src);
    }

    // Q weights for this thread's m-columns: m1=2t, m2=2t+1, m8=8.
    const int twot = 2 * t;
    const int a1 = twot / 3, b1 = twot % 3;
    const int a2 = (twot + 1) / 3, b2 = (twot + 1) % 3;
    float Q1[4], Q2[4], Q8v[4];
#pragma unroll
    for (int s = 0; s < 4; s++) {
        float u0a = (a1 == 0) ? 1.0f : ((a1 == 1) ? uc0[s] : us0[s]);
        float u1b = (b1 == 0) ? 1.0f : ((b1 == 1) ? uc1[s] : us1[s]);
        Q1[s] = u0a * u1b;
        float u0a2 = (a2 == 0) ? 1.0f : ((a2 == 1) ? uc0[s] : us0[s]);
        float u1b2 = (b2 == 0) ? 1.0f : ((b2 == 1) ? uc1[s] : us1[s]);
        Q2[s] = u0a2 * u1b2;
        Q8v[s] = us0[s] * us1[s];
    }

    // ================= acquire constants, stage B =================
    if (tid < 40) {
        if (blockIdx.x != 0) {
            int f;
            asm volatile("ld.acquire.gpu.global.s32 %0, [%1];" : "=r"(f) : "l"(&gFlag) : "memory");
            while (f == 0) {
                __nanosleep(64);
                asm volatile("ld.acquire.gpu.global.s32 %0, [%1];" : "=r"(f) : "l"(&gFlag) : "memory");
            }
        }
        const uint4* gp = reinterpret_cast<const uint4*>(gB16) + tid * 4;
        uint32_t base = smb + SM_B + (uint32_t)tid * 80;
#pragma unroll
        for (int q = 0; q < 4; q++) {
            uint4 v = gp[q];
            sts128(base + q * 16, v.x, v.y, v.z, v.w);
        }
    }
    __syncthreads();

    // ================= A fragments =================
    const int l15 = lane & 15;
    uint32_t a[2][2][4];     // [kt][mt][reg]
#pragma unroll
    for (int kt = 0; kt < 2; kt++)
#pragma unroll
        for (int mt = 0; mt < 2; mt++) {
            uint32_t addr = smb + SM_A +
                (uint32_t)(wid * 32 + mt * 16 + l15) * 80 +
                ((lane >> 4) * 16) + kt * 32;
            ldm_x4(a[kt][mt], addr);
        }

    // ================= per-nt MMA + fragment-domain epilogue ==============
    float out[4][4];   // [slot][w]
#pragma unroll
    for (int s = 0; s < 4; s++)
#pragma unroll
        for (int w = 0; w < 4; w++) out[s][w] = 0.0f;

#pragma unroll
    for (int nt = 0; nt < 5; nt++) {
        float d[2][4];
#pragma unroll
        for (int mt = 0; mt < 2; mt++)
#pragma unroll
            for (int i = 0; i < 4; i++) d[mt][i] = 0.0f;
#pragma unroll
        for (int kt = 0; kt < 2; kt++) {
            uint32_t b0, b1v;
            uint32_t addr = smb + SM_B +
                (uint32_t)(nt * 8 + (l15 & 7)) * 80 +
                (((l15 >> 3) & 1) * 16) + kt * 32;
            ldm_x2(b0, b1v, addr);
#pragma unroll
            for (int mt = 0; mt < 2; mt++)
                mma16816(d[mt], a[kt][mt], b0, b1v);
        }
        // d[mt]: d0=(row g, col 2t), d1=(row g, 2t+1), d2=(row g+8, 2t), d3=(g+8, 2t+1)
        if (nt < 4) {
#pragma unroll
            for (int s = 0; s < 4; s++) {
                const int mt = s >> 1, h = s & 1;
                float de0 = h ? d[mt][2] : d[mt][0];
                float de1 = h ? d[mt][3] : d[mt][1];
                out[s][nt] = fmaf(Q1[s], de0, out[s][nt]);
                out[s][nt] = fmaf(Q2[s], de1, out[s][nt]);
            }
        } else {
            // columns (w=2t+e, m=8); valid only for t<2 (rows 36..39 of B are 0)
            if (t == 0) {
#pragma unroll
                for (int s = 0; s < 4; s++) {
                    const int mt = s >> 1, h = s & 1;
                    float de0 = h ? d[mt][2] : d[mt][0];
                    float de1 = h ? d[mt][3] : d[mt][1];
                    out[s][0] = fmaf(Q8v[s], de0, out[s][0]);
                    out[s][1] = fmaf(Q8v[s], de1, out[s][1]);
                }
            } else if (t == 1) {
#pragma unroll
                for (int s = 0; s < 4; s++) {
                    const int mt = s >> 1, h = s & 1;
                    float de0 = h ? d[mt][2] : d[mt][0];
                    float de1 = h ? d[mt][3] : d[mt][1];
                    out[s][2] = fmaf(Q8v[s], de0, out[s][2]);
                    out[s][3] = fmaf(Q8v[s], de1, out[s][3]);
                }
            }
        }
    }

    // ================= reduce over the 4-lane t-group =================
#pragma unroll
    for (int s = 0; s < 4; s++)
#pragma unroll
        for (int w = 0; w < 4; w++) {
            float v = out[s][w];
            v += __shfl_xor_sync(0xffffffffu, v, 1);
            v += __shfl_xor_sync(0xffffffffu, v, 2);
            out[s][w] = v;
        }

    // ================= store: lane t writes slot s==t =================
#pragma unroll
    for (int s = 0; s < 4; s++) {
        if (t == s) {
            int row = blockIdx.x * TPB + wid * 32 + (s >> 1) * 16 + (s & 1) * 8 + g;
            if (row < nSamples)
                xout[row] = make_float4(out[s][0], out[s][1], out[s][2], out[s][3]);
        }
    }
}

extern "C" void kernel_launch(void* const* d_in, const int* in_sizes, int n_in,
                              void* d_out, int out_size) {
    // Identify tensors by size: q_weights is tiny (nlayers*4*3), inputs is B*4.
    int xi = 0, wi = 1;
    if (n_in >= 2 && in_sizes[0] < in_sizes[1]) { xi = 1; wi = 0; }
    const float* x  = (const float*)d_in[xi];
    const float* qw = (const float*)d_in[wi];
    int B = in_sizes[xi] / 4;
    int nlayers = in_sizes[wi] / 12;

    int blocks = (B + TPB - 1) / TPB;
    qmma_kernel<<<blocks, TPB, SM_TOTAL>>>((const float4*)x, (float4*)d_out,
                                           qw, nlayers, B);
}

// round 17
// speedup vs baseline: 1.1523x; 1.1523x over previous
#include <cuda_runtime.h>
#include <cuda_bf16.h>
#include <cstdint>

typedef unsigned long long ull;

#define TPB 128

// fp32-path constants: G_w[m][n] f32x2-duplicated, padded stride-10 rows.
__device__ __align__(16) ull gGd[360];
// MMA-path B matrix: 40 rows (j=w*9+m; rows 36..39 zero) x 32 k-cols bf16:
// k 0..8 = Ghi, 9..17 = Glo, 18..26 = Ghi, 27..31 zero. Zero-init persists.
__device__ __align__(16) unsigned short gB16[40 * 32];
// Publish flag: 0 only before the very first launch; graph replays never wait.
__device__ int gFlag = 0;

// ---------------- f32x2 helpers ----------------
__device__ __forceinline__ ull ffma2(ull a, ull b, ull c) {
    ull d;
    asm("fma.rn.f32x2 %0, %1, %2, %3;" : "=l"(d) : "l"(a), "l"(b), "l"(c));
    return d;
}
__device__ __forceinline__ ull pk(float lo, float hi) {
    ull r;
    unsigned int l = __float_as_uint(lo), h = __float_as_uint(hi);
    asm("mov.b64 %0, {%1, %2};" : "=l"(r) : "r"(l), "r"(h));
    return r;
}
__device__ __forceinline__ void upk(ull v, float &lo, float &hi) {
    unsigned int l, h;
    asm("mov.b64 {%0, %1}, %2;" : "=r"(l), "=r"(h) : "l"(v));
    lo = __uint_as_float(l);
    hi = __uint_as_float(h);
}
// ---------------- MMA helpers ----------------
__device__ __forceinline__ uint32_t smem_u32(const void* p) {
    uint32_t a;
    asm("{ .reg .u64 t; cvta.to.shared.u64 t, %1; cvt.u32.u64 %0, t; }"
        : "=r"(a) : "l"(p));
    return a;
}
__device__ __forceinline__ void sts128(uint32_t addr, uint32_t a, uint32_t b,
                                       uint32_t c, uint32_t d) {
    asm volatile("st.shared.v4.b32 [%0], {%1,%2,%3,%4};"
                 :: "r"(addr), "r"(a), "r"(b), "r"(c), "r"(d) : "memory");
}
__device__ __forceinline__ void ldm_x4(uint32_t* r, uint32_t addr) {
    asm volatile("ldmatrix.sync.aligned.m8n8.x4.shared.b16 {%0,%1,%2,%3}, [%4];"
                 : "=r"(r[0]), "=r"(r[1]), "=r"(r[2]), "=r"(r[3]) : "r"(addr));
}
__device__ __forceinline__ void ldm_x2(uint32_t& b0, uint32_t& b1, uint32_t addr) {
    asm volatile("ldmatrix.sync.aligned.m8n8.x2.shared.b16 {%0,%1}, [%2];"
                 : "=r"(b0), "=r"(b1) : "r"(addr));
}
__device__ __forceinline__ void mma16816(float* d, const uint32_t* a,
                                         uint32_t b0, uint32_t b1) {
    asm volatile(
        "mma.sync.aligned.m16n8k16.row.col.f32.bf16.bf16.f32 "
        "{%0,%1,%2,%3}, {%4,%5,%6,%7}, {%8,%9}, {%0,%1,%2,%3};"
        : "+f"(d[0]), "+f"(d[1]), "+f"(d[2]), "+f"(d[3])
        : "r"(a[0]), "r"(a[1]), "r"(a[2]), "r"(a[3]), "r"(b0), "r"(b1));
}

// ---------------- dynamic shared layout ----------------
// MMA blocks:  A [0,10240) 128x80B; D overlays A, col-major 40x132 f32
//              [0,21120); B [21120,24320) 40x80B.
// fp32 blocks: sG ull[360] at [0,2880).
// block 0 setup scratch: [0, ~8.2KB) — dead before any path smem writes.
#define SM_A 0
#define SM_D 0
#define SM_B 21120
#define SM_TOTAL 24320
#define DCOL 132

__global__ void __launch_bounds__(TPB, 6) qhyb_kernel(
    const float4* __restrict__ xin, float* __restrict__ xout,
    const float* __restrict__ qw, int nlayers, int halfB,
    int NF, int NB, int PF, int Lc) {
    extern __shared__ char sm[];
    const uint32_t smb = smem_u32(sm);
    const int tid = threadIdx.x;
    const int wid = tid >> 5;
    const int lane = tid & 31;
    const int bid = blockIdx.x;

    // ================= block 0: build BOTH constant sets =================
    if (bid == 0) {
        float (*Mr)[16] = (float(*)[16])(sm);
        float (*Mi)[16] = (float(*)[16])(sm + 1024);
        float* bufA = (float*)(sm + 2048) + wid * 256;
        float* bufB = (float*)(sm + 6144) + wid * 192;

        if (tid < 16) {
            float mr[16], mi[16];
#pragma unroll
            for (int r = 0; r < 16; r++) { mr[r] = (r == tid) ? 1.0f : 0.0f; mi[r] = 0.0f; }
            for (int l = 0; l < nlayers; l++) {
#pragma unroll
                for (int w = 0; w < 4; w++) {
                    float phi = qw[(l * 4 + w) * 3 + 0];
                    float th  = qw[(l * 4 + w) * 3 + 1];
                    float om  = qw[(l * 4 + w) * 3 + 2];
                    float c, s, ca, sa, cb, sb;
                    __sincosf(0.5f * th, &s, &c);
                    __sincosf(0.5f * (phi + om), &sa, &ca);
                    __sincosf(0.5f * (phi - om), &sb, &cb);
                    float g00r =  ca * c, g00i = -sa * c;
                    float g01r = -cb * s, g01i = -sb * s;
                    float g10r =  cb * s, g10i = -sb * s;
                    float g11r =  ca * c, g11i =  sa * c;
                    const int mu = 8 >> w;
#pragma unroll
                    for (int r = 0; r < 16; r++) {
                        if (r & mu) continue;
                        const int r1 = r | mu;
                        float ar = mr[r],  ai = mi[r];
                        float br = mr[r1], bi = mi[r1];
                        mr[r]  = g00r * ar - g00i * ai + g01r * br - g01i * bi;
                        mi[r]  = g00r * ai + g00i * ar + g01r * bi + g01i * br;
                        mr[r1] = g10r * ar - g10i * ai + g11r * br - g11i * bi;
                        mi[r1] = g10r * ai + g10i * ar + g11r * bi + g11i * br;
                    }
                }
#pragma unroll
                for (int w = 0; w < 4; w++) {
                    const int cm = 8 >> w;
                    const int tm = 8 >> ((w + 1) & 3);
#pragma unroll
                    for (int r = 0; r < 16; r++) {
                        if ((r & cm) && !(r & tm)) {
                            const int r2 = r | tm;
                            float t;
                            t = mr[r]; mr[r] = mr[r2]; mr[r2] = t;
                            t = mi[r]; mi[r] = mi[r2]; mi[r2] = t;
                        }
                    }
                }
            }
#pragma unroll
            for (int r = 0; r < 16; r++) { Mr[r][tid] = mr[r]; Mi[r][tid] = mi[r]; }
        }
        __syncthreads();

        {   // warp w builds G_w, writes BOTH gGd (f32x2) and gB16 (bf16 split)
            const int w = wid;
            const int mw = 8 >> w;
            for (int e = lane; e < 256; e += 32) {
                int i = e / 16, j = e % 16;
                float sum = 0.0f;
                for (int k = 0; k < 16; k++) {
                    float sgn = (k & mw) ? -1.0f : 1.0f;
                    sum += sgn * (Mr[k][i] * Mr[k][j] + Mi[k][i] * Mi[k][j]);
                }
                int b0 = 0;
                for (int q = 0; q < 4; q++) {
                    int iw = (i >> (3 - q)) & 1;
                    int jw = (j >> (3 - q)) & 1;
                    b0 = b0 * 4 + (iw * 2 + jw);
                }
                bufA[b0] = sum;
            }
            __syncwarp();
            float* bin = bufA;
            float* bout = bufB;
            int pre = 1, post = 64;
            for (int q = 0; q < 4; q++) {
                int nout = pre * 3 * post;
                for (int e = lane; e < nout; e += 32) {
                    int po = e % post;
                    int al = (e / post) % 3;
                    int pr2 = e / (post * 3);
                    const float* ip = bin + pr2 * 4 * post;
                    float v;
                    if (al == 0)      v = 0.5f * (ip[0 * post + po] + ip[3 * post + po]);
                    else if (al == 1) v = 0.5f * (ip[0 * post + po] - ip[3 * post + po]);
                    else              v = 0.5f * (ip[1 * post + po] + ip[2 * post + po]);
                    bout[pr2 * 3 * post + al * post + po] = v;
                }
                __syncwarp();
                float* t = bin; bin = bout; bout = t;
                pre *= 3; post /= 4;
            }
            for (int e = lane; e < 81; e += 32) {
                int m = e / 9, n = e % 9;
                float v = bin[e];
                unsigned int bits = __float_as_uint(v);
                gGd[w * 90 + m * 10 + n] = ((ull)bits << 32) | (ull)bits;
                __nv_bfloat16 h = __float2bfloat16(v);
                float hf = __bfloat162float(h);
                __nv_bfloat16 l2 = __float2bfloat16(v - hf);
                int row = w * 9 + m;
                gB16[row * 32 + n]      = __bfloat16_as_ushort(h);
                gB16[row * 32 + 9 + n]  = __bfloat16_as_ushort(l2);
                gB16[row * 32 + 18 + n] = __bfloat16_as_ushort(h);
            }
        }
        __syncthreads();
        if (tid == 0) {
            __threadfence();
            int one = 1;
            asm volatile("st.release.gpu.global.s32 [%0], %1;"
                         :: "l"(&gFlag), "r"(one) : "memory");
        }
        __syncthreads();   // setup scratch dead before path smem use
    } else {
        if (tid == 0) {
            int f;
            asm volatile("ld.acquire.gpu.global.s32 %0, [%1];" : "=r"(f) : "l"(&gFlag) : "memory");
            while (f == 0) {
                __nanosleep(64);
                asm volatile("ld.acquire.gpu.global.s32 %0, [%1];" : "=r"(f) : "l"(&gFlag) : "memory");
            }
        }
        __syncthreads();
    }

    // ================= block-type dispatch (Bresenham interleave) =========
    const long long fiL = ((long long)bid * NF) / NB;
    const bool is_fp32 = (((long long)(bid + 1) * NF) / NB) > fiL;
    const int fi = (int)fiL;

    if (is_fp32) {
        // ============== fp32 path (R12, verbatim; pairs fi*256+tid) ========
        ull* sG = (ull*)sm;
        for (int i = tid; i < 360; i += TPB) sG[i] = gGd[i];
        __syncthreads();

        int p0 = fi * 256 + tid;
        int p1 = p0 + TPB;
        if (p0 >= halfB) p0 = halfB - 1;
        if (p1 >= halfB) p1 = halfB - 1;
        float4 x0a = xin[p0];
        float4 x0b = xin[p0 + halfB];
        float4 x1a = xin[p1];
        float4 x1b = xin[p1 + halfB];

        ull C0[2], S0[2], C1[2], S1[2], C2[2], S2[2], C3[2], S3[2];
        {
            float ca, sa, cb, sb;
            __sincosf(x0a.x, &sa, &ca); __sincosf(x0b.x, &sb, &cb);
            C0[0] = pk(ca, cb);  S0[0] = pk(sa, sb);
            __sincosf(x0a.y, &sa, &ca); __sincosf(x0b.y, &sb, &cb);
            C1[0] = pk(ca, cb);  S1[0] = pk(sa, sb);
            __sincosf(x0a.z, &sa, &ca); __sincosf(x0b.z, &sb, &cb);
            C2[0] = pk(ca, cb);  S2[0] = pk(sa, sb);
            __sincosf(x0a.w, &sa, &ca); __sincosf(x0b.w, &sb, &cb);
            C3[0] = pk(ca, cb);  S3[0] = pk(sa, sb);
            __sincosf(x1a.x, &sa, &ca); __sincosf(x1b.x, &sb, &cb);
            C0[1] = pk(ca, cb);  S0[1] = pk(sa, sb);
            __sincosf(x1a.y, &sa, &ca); __sincosf(x1b.y, &sb, &cb);
            C1[1] = pk(ca, cb);  S1[1] = pk(sa, sb);
            __sincosf(x1a.z, &sa, &ca); __sincosf(x1b.z, &sb, &cb);
            C2[1] = pk(ca, cb);  S2[1] = pk(sa, sb);
            __sincosf(x1a.w, &sa, &ca); __sincosf(x1b.w, &sb, &cb);
            C3[1] = pk(ca, cb);  S3[1] = pk(sa, sb);
        }

#pragma unroll
        for (int w = 0; w < 4; w++) {
            ull acc0[2], acc1[2], acc2[2];
#pragma unroll
            for (int m = 0; m < 9; m++) {
                const int off = w * 90 + m * 10;
                const ulonglong2* rp = reinterpret_cast<const ulonglong2*>(&sG[off]);
                ulonglong2 gA = rp[0];
                ulonglong2 gB = rp[1];
                ulonglong2 gC = rp[2];
                ulonglong2 gD = rp[3];
                ull g8 = sG[off + 8];
                const int a = m / 3, b = m % 3;
#pragma unroll
                for (int p = 0; p < 2; p++) {
                    ull t0 = ffma2(C3[p], gA.y, gA.x);
                    t0 = ffma2(S3[p], gB.x, t0);
                    ull t1 = ffma2(C3[p], gC.x, gB.y);
                    t1 = ffma2(S3[p], gC.y, t1);
                    ull t2 = ffma2(C3[p], gD.y, gD.x);
                    t2 = ffma2(S3[p], g8, t2);
                    ull r = ffma2(C2[p], t1, t0);
                    r = ffma2(S2[p], t2, r);
                    ull* A = (a == 0) ? &acc0[p] : (a == 1) ? &acc1[p] : &acc2[p];
                    if (b == 0)      *A = r;
                    else if (b == 1) *A = ffma2(C1[p], r, *A);
                    else             *A = ffma2(S1[p], r, *A);
                }
            }
#pragma unroll
            for (int p = 0; p < 2; p++) {
                ull o = ffma2(C0[p], acc1[p], acc0[p]);
                o = ffma2(S0[p], acc2[p], o);
                float lo, hi;
                upk(o, lo, hi);
                int idx = (p == 0) ? p0 : p1;
                xout[idx * 4 + w]           = lo;
                xout[(idx + halfB) * 4 + w] = hi;
            }
        }
    } else {
        // ============== MMA path (R15, verbatim; 128 samples at s0) ========
        const int mi = bid - fi;
        const int s0 = (mi < Lc) ? (PF + mi * TPB)
                                 : (halfB + PF + (mi - Lc) * TPB);
        const int idx = s0 + tid;

        float4 x = xin[idx];
        float c0, s0t, c1, s1, c2, s2, c3, s3;
        __sincosf(x.x, &s0t, &c0);
        __sincosf(x.y, &s1, &c1);
        __sincosf(x.z, &s2, &c2);
        __sincosf(x.w, &s3, &c3);

        {
            float P[9];
            P[0] = 1.0f; P[1] = c3;      P[2] = s3;
            P[3] = c2;   P[4] = c2 * c3; P[5] = c2 * s3;
            P[6] = s2;   P[7] = s2 * c3; P[8] = s2 * s3;

            unsigned short F[32];
#pragma unroll
            for (int k = 0; k < 32; k++) F[k] = 0;
#pragma unroll
            for (int n = 0; n < 9; n++) {
                __nv_bfloat16 h = __float2bfloat16(P[n]);
                float hf = __bfloat162float(h);
                __nv_bfloat16 l2 = __float2bfloat16(P[n] - hf);
                unsigned short hb = __bfloat16_as_ushort(h);
                F[n] = hb;
                F[9 + n] = hb;
                F[18 + n] = __bfloat16_as_ushort(l2);
            }
            uint32_t w32[16];
#pragma unroll
            for (int j = 0; j < 16; j++)
                w32[j] = (uint32_t)F[2 * j] | ((uint32_t)F[2 * j + 1] << 16);

            uint32_t base = smb + SM_A + (uint32_t)tid * 80;
            sts128(base,      w32[0],  w32[1],  w32[2],  w32[3]);
            sts128(base + 16, w32[4],  w32[5],  w32[6],  w32[7]);
            sts128(base + 32, w32[8],  w32[9],  w32[10], w32[11]);
            sts128(base + 48, w32[12], w32[13], w32[14], w32[15]);
        }

        if (tid < 40) {
            const uint4* gp = reinterpret_cast<const uint4*>(gB16) + tid * 4;
            uint32_t base = smb + SM_B + (uint32_t)tid * 80;
#pragma unroll
            for (int q = 0; q < 4; q++) {
                uint4 v = gp[q];
                sts128(base + q * 16, v.x, v.y, v.z, v.w);
            }
        }
        __syncthreads();

        const int l15 = lane & 15;
        uint32_t a[2][2][4];
        uint32_t bf[2][5][2];
#pragma unroll
        for (int kt = 0; kt < 2; kt++) {
#pragma unroll
            for (int mt = 0; mt < 2; mt++) {
                uint32_t addr = smb + SM_A +
                    (uint32_t)(wid * 32 + mt * 16 + l15) * 80 +
                    ((lane >> 4) * 16) + kt * 32;
                ldm_x4(a[kt][mt], addr);
            }
#pragma unroll
            for (int nt = 0; nt < 5; nt++) {
                uint32_t addr = smb + SM_B +
                    (uint32_t)(nt * 8 + (l15 & 7)) * 80 +
                    (((l15 >> 3) & 1) * 16) + kt * 32;
                ldm_x2(bf[kt][nt][0], bf[kt][nt][1], addr);
            }
        }
        __syncthreads();   // A fully read; D may overlay it

        float d[2][5][4];
#pragma unroll
        for (int mt = 0; mt < 2; mt++)
#pragma unroll
            for (int nt = 0; nt < 5; nt++)
#pragma unroll
                for (int i = 0; i < 4; i++) d[mt][nt][i] = 0.0f;
#pragma unroll
        for (int kt = 0; kt < 2; kt++)
#pragma unroll
            for (int nt = 0; nt < 5; nt++)
#pragma unroll
                for (int mt = 0; mt < 2; mt++)
                    mma16816(d[mt][nt], a[kt][mt], bf[kt][nt][0], bf[kt][nt][1]);

        float* Ds = (float*)(sm + SM_D);
#pragma unroll
        for (int mt = 0; mt < 2; mt++)
#pragma unroll
            for (int nt = 0; nt < 5; nt++)
#pragma unroll
                for (int i = 0; i < 4; i++) {
                    int col = nt * 8 + (lane & 3) * 2 + (i & 1);
                    int row = wid * 32 + mt * 16 + (lane >> 2) + ((i >> 1) << 3);
                    Ds[col * DCOL + row] = d[mt][nt][i];
                }
        __syncwarp();

        float o[4];
#pragma unroll
        for (int w = 0; w < 4; w++) {
            const int b = w * 9;
            float R0 = Ds[(b + 0) * DCOL + tid];
            float R1 = Ds[(b + 1) * DCOL + tid];
            float R2 = Ds[(b + 2) * DCOL + tid];
            float R3 = Ds[(b + 3) * DCOL + tid];
            float R4 = Ds[(b + 4) * DCOL + tid];
            float R5 = Ds[(b + 5) * DCOL + tid];
            float R6 = Ds[(b + 6) * DCOL + tid];
            float R7 = Ds[(b + 7) * DCOL + tid];
            float R8 = Ds[(b + 8) * DCOL + tid];
            float a0 = fmaf(s1, R2, fmaf(c1, R1, R0));
            float a1 = fmaf(s1, R5, fmaf(c1, R4, R3));
            float a2 = fmaf(s1, R8, fmaf(c1, R7, R6));
            o[w] = fmaf(s0t, a2, fmaf(c0, a1, a0));
        }
        reinterpret_cast<float4*>(xout)[idx] = make_float4(o[0], o[1], o[2], o[3]);
    }
}

extern "C" void kernel_launch(void* const* d_in, const int* in_sizes, int n_in,
                              void* d_out, int out_size) {
    // Identify tensors by size: q_weights is tiny (nlayers*4*3), inputs is B*4.
    int xi = 0, wi = 1;
    if (n_in >= 2 && in_sizes[0] < in_sizes[1]) { xi = 1; wi = 0; }
    const float* x  = (const float*)d_in[xi];
    const float* qw = (const float*)d_in[wi];
    int B = in_sizes[xi] / 4;
    int nlayers = in_sizes[wi] / 12;
    int halfB = B / 2;

    int NF, NB, PF, Lc;
    if ((B % 2 == 0) && (halfB % 256 == 0) && halfB >= 1024) {
        // x = 0.55 of pairs go to the fp32 path
        PF = (int)(((long long)halfB * 55) / 100);
        PF -= PF % 256;
        if (PF < 256) PF = 256;
        if (PF > halfB - 256) PF = halfB - 256;
        int L = halfB - PF;          // multiple of 256
        Lc = L / TPB;                // MMA chunks per range
        NF = PF / 256;
        NB = NF + 2 * Lc;
    } else {
        PF = halfB;
        NF = (halfB + 255) / 256;
        NB = NF;
        Lc = 0;
    }

    qhyb_kernel<<<NB, TPB, SM_TOTAL>>>((const float4*)x, (float*)d_out, qw,
                                       nlayers, halfB, NF, NB, PF, Lc);
}